// round 10
// baseline (speedup 1.0000x reference)
#include <cuda_runtime.h>
#include <cuda_bf16.h>
#include <math.h>
#include <stdint.h>

#define N_TOT 8192
#define F_DIM 128
#define TBLK  64                 // 8192 / 128
#define NTILES (TBLK*(TBLK+1)/2) // 2080 upper-triangle tiles
#define TILEB 16384              // 128 rows x 128B (fp8), XOR-swizzled
#define SM_TOTAL (2 * TILEB)     // A + B = 32KB

// Device scratch (allocation-free rules)
__device__ uint8_t g_x8[N_TOT * F_DIM];   // scaled normalized feats [N][F] e4m3
__device__ float g_part[NTILES];

__device__ __forceinline__ uint32_t smem_u32(const void* p) {
    uint32_t a;
    asm("{ .reg .u64 t; cvta.to.shared.u64 t, %1; cvt.u32.u64 %0, t; }" : "=r"(a) : "l"(p));
    return a;
}
__device__ __forceinline__ float ex2a(float x) {
    float y; asm("ex2.approx.f32 %0, %1;" : "=f"(y) : "f"(x)); return y;
}
// pack 4 floats -> 4 e4m3 bytes (v0 lowest byte)
__device__ __forceinline__ uint32_t fp8x4(float v0, float v1, float v2, float v3) {
    uint16_t lo, hi;
    asm("cvt.rn.satfinite.e4m3x2.f32 %0, %2, %1;" : "=h"(lo) : "f"(v0), "f"(v1));
    asm("cvt.rn.satfinite.e4m3x2.f32 %0, %2, %1;" : "=h"(hi) : "f"(v2), "f"(v3));
    return (uint32_t)lo | ((uint32_t)hi << 16);
}
#define CPA16(dst, src) \
    asm volatile("cp.async.cg.shared.global [%0], [%1], 16;" :: "r"(dst), "l"(src))

// ---------------------------------------------------------------------------
// Kernel 1: normalize + fold sqrt(10/ln2) + e4m3 convert. 16 rows per block.
// ---------------------------------------------------------------------------
__global__ void __launch_bounds__(256) normalize_kernel(const float* __restrict__ x) {
    __shared__ float sm[16 * 130];
    __shared__ float ssp[16][17];
    __shared__ float rn[16];

    const int tid = threadIdx.x;
    const int n0  = blockIdx.x * 16;
    const int b   = n0 >> 10;
    const int thw0 = n0 & 1023;
    const float* base = x + (size_t)b * 131072 + thw0;

#pragma unroll
    for (int it = 0; it < 2; ++it) {
        int idx = it * 256 + tid;
        int q = idx & 3;
        int f = idx >> 2;
        float4 v = *(const float4*)&base[(size_t)f * 1024 + q * 4];
        sm[(q * 4 + 0) * 130 + f] = v.x;
        sm[(q * 4 + 1) * 130 + f] = v.y;
        sm[(q * 4 + 2) * 130 + f] = v.z;
        sm[(q * 4 + 3) * 130 + f] = v.w;
    }
    __syncthreads();
    {
        int r = tid & 15, part = tid >> 4;
        float ss = 0.f;
#pragma unroll
        for (int f = part * 8; f < part * 8 + 8; ++f) {
            float v = sm[r * 130 + f];
            ss += v * v;
        }
        ssp[part][r] = ss;
    }
    __syncthreads();
    if (tid < 16) {
        float ss = 0.f;
#pragma unroll
        for (int p = 0; p < 16; ++p) ss += ssp[p][tid];
        // 3.7982825 = sqrt(10 / ln 2): folds the exp2 scale into the data
        rn[tid] = (1.0f / fmaxf(sqrtf(ss), 1e-12f)) * 3.7982825f;
    }
    __syncthreads();
    uint32_t* out = (uint32_t*)(g_x8 + (size_t)n0 * F_DIM);
#pragma unroll
    for (int it = 0; it < 2; ++it) {
        int idx = it * 256 + tid;     // 512 u32 words total (16 rows x 32)
        int f4 = idx & 31;            // u32 column (4 features)
        int r  = idx >> 5;
        float s = rn[r];
        const float* p = &sm[r * 130 + f4 * 4];
        out[r * 32 + f4] = fp8x4(p[0] * s, p[1] * s, p[2] * s, p[3] * s);
    }
}

// ---------------------------------------------------------------------------
// Kernel 2: FP8 e4m3 MMA (m16n8k32) 128x128x128 tile + fused exp2-sum.
// 16 warps, 32x32 warp tiles. Tile rows 128B, XOR-swizzled 16B chunks.
// ---------------------------------------------------------------------------
__global__ void __launch_bounds__(512, 2) simexp_kernel() {
    extern __shared__ char smem[];
    const uint32_t sbase = smem_u32(smem);
    const int tid  = threadIdx.x;
    const int wid  = tid >> 5;
    const int lane = tid & 31;

    // linear tile id -> (bi, bj), bj >= bi
    int t = blockIdx.x;
    int bi = (int)((129.0f - sqrtf(16641.0f - 8.0f * (float)t)) * 0.5f);
    while ((bi + 1) * (129 - (bi + 1)) / 2 <= t) ++bi;
    while (bi * (129 - bi) / 2 > t) --bi;
    const int bj = bi + (t - bi * (129 - bi) / 2);
    const bool diag = (bi == bj);

    // cooperative tile loads (1024 x 16B chunks over 512 threads)
    {
        const char* gA = (const char*)(g_x8 + (size_t)bi * 128 * F_DIM);
#pragma unroll
        for (int it = 0; it < 2; ++it) {
            int idx = it * 512 + tid;
            int r = idx >> 3, q = idx & 7;
            CPA16(sbase + r * 128 + ((q ^ (r & 7)) << 4), gA + (size_t)idx * 16);
        }
        if (!diag) {
            const char* gB = (const char*)(g_x8 + (size_t)bj * 128 * F_DIM);
#pragma unroll
            for (int it = 0; it < 2; ++it) {
                int idx = it * 512 + tid;
                int r = idx >> 3, q = idx & 7;
                CPA16(sbase + TILEB + r * 128 + ((q ^ (r & 7)) << 4), gB + (size_t)idx * 16);
            }
        }
        asm volatile("cp.async.commit_group;");
        asm volatile("cp.async.wait_group 0;" ::: "memory");
    }
    __syncthreads();

    const uint32_t aBase = sbase;
    const uint32_t bBase = diag ? sbase : (sbase + TILEB);

    const int wm = (wid >> 2) * 32;   // 4x4 warp grid
    const int wn = (wid & 3) * 32;
    const int g  = lane >> 3;
    const int lr = lane & 7;
    const int lrow = lane >> 2;
    const int lcol = (lane & 3) * 2;

    float acc[2][4][4];
#pragma unroll
    for (int mt = 0; mt < 2; ++mt)
#pragma unroll
        for (int nt = 0; nt < 4; ++nt)
#pragma unroll
            for (int c = 0; c < 4; ++c) acc[mt][nt][c] = 0.f;

#pragma unroll
    for (int kc = 0; kc < 4; ++kc) {      // K=128 in chunks of 32 (fp8)
        const int qa = kc * 2 + (g >> 1); // A: mats {r0-7,B0},{r8-15,B0},{r0-7,B1},{r8-15,B1}
        const int qb = kc * 2 + (g & 1);  // B: mats {n0-7,B0},{n0-7,B1},{n8-15,B0},{n8-15,B1}
        uint32_t a[2][4];
#pragma unroll
        for (int mt = 0; mt < 2; ++mt) {
            int row = wm + mt * 16 + (g & 1) * 8 + lr;   // row & 7 == lr
            uint32_t addr = aBase + row * 128 + ((qa ^ lr) << 4);
            asm volatile("ldmatrix.sync.aligned.m8n8.x4.shared.b16 {%0,%1,%2,%3}, [%4];"
                         : "=r"(a[mt][0]), "=r"(a[mt][1]), "=r"(a[mt][2]), "=r"(a[mt][3])
                         : "r"(addr));
        }
        uint32_t bf[2][4];
#pragma unroll
        for (int np = 0; np < 2; ++np) {
            int row = wn + np * 16 + (g >> 1) * 8 + lr;  // row & 7 == lr
            uint32_t addr = bBase + row * 128 + ((qb ^ lr) << 4);
            asm volatile("ldmatrix.sync.aligned.m8n8.x4.shared.b16 {%0,%1,%2,%3}, [%4];"
                         : "=r"(bf[np][0]), "=r"(bf[np][1]), "=r"(bf[np][2]), "=r"(bf[np][3])
                         : "r"(addr));
        }
#pragma unroll
        for (int mt = 0; mt < 2; ++mt)
#pragma unroll
            for (int nt = 0; nt < 4; ++nt) {
                uint32_t b0 = bf[nt >> 1][(nt & 1) * 2];
                uint32_t b1 = bf[nt >> 1][(nt & 1) * 2 + 1];
                asm volatile(
                    "mma.sync.aligned.m16n8k32.row.col.f32.e4m3.e4m3.f32 "
                    "{%0,%1,%2,%3}, {%4,%5,%6,%7}, {%8,%9}, {%0,%1,%2,%3};"
                    : "+f"(acc[mt][nt][0]), "+f"(acc[mt][nt][1]),
                      "+f"(acc[mt][nt][2]), "+f"(acc[mt][nt][3])
                    : "r"(a[mt][0]), "r"(a[mt][1]), "r"(a[mt][2]), "r"(a[mt][3]),
                      "r"(b0), "r"(b1));
            }
    }

    // epilogue: scale pre-folded -> bare 2^acc; skip i==j on diag tiles
    float s = 0.f;
#pragma unroll
    for (int mt = 0; mt < 2; ++mt)
#pragma unroll
        for (int nt = 0; nt < 4; ++nt)
#pragma unroll
            for (int c = 0; c < 4; ++c) {
                int r_ = wm + mt * 16 + ((c >> 1) << 3) + lrow;
                int c_ = wn + nt * 8 + lcol + (c & 1);
                if (diag && r_ == c_) continue;
                s += ex2a(acc[mt][nt][c]);
            }
    if (!diag) s *= 2.f;

    __shared__ float red[16];
#pragma unroll
    for (int off = 16; off > 0; off >>= 1)
        s += __shfl_down_sync(0xFFFFFFFFu, s, off);
    if (lane == 0) red[wid] = s;
    __syncthreads();
    if (tid == 0) {
        float tsum = 0.f;
#pragma unroll
        for (int w = 0; w < 16; ++w) tsum += red[w];
        g_part[blockIdx.x] = tsum;
    }
}

// ---------------------------------------------------------------------------
// Kernel 3: deterministic final reduction + log
// ---------------------------------------------------------------------------
__global__ void __launch_bounds__(256) finalize_kernel(float* __restrict__ out) {
    __shared__ float red[8];
    float s = 0.f;
    for (int i = threadIdx.x; i < NTILES; i += 256) s += g_part[i];
#pragma unroll
    for (int off = 16; off > 0; off >>= 1)
        s += __shfl_down_sync(0xFFFFFFFFu, s, off);
    if ((threadIdx.x & 31) == 0) red[threadIdx.x >> 5] = s;
    __syncthreads();
    if (threadIdx.x == 0) {
        float tsum = 0.f;
#pragma unroll
        for (int w = 0; w < 8; ++w) tsum += red[w];
        out[0] = logf(tsum);
    }
}

extern "C" void kernel_launch(void* const* d_in, const int* in_sizes, int n_in,
                              void* d_out, int out_size) {
    const float* x = (const float*)d_in[0];
    float* out = (float*)d_out;
    (void)in_sizes; (void)n_in; (void)out_size;

    cudaFuncSetAttribute(simexp_kernel, cudaFuncAttributeMaxDynamicSharedMemorySize, SM_TOTAL);

    normalize_kernel<<<N_TOT / 16, 256>>>(x);
    simexp_kernel<<<NTILES, 512, SM_TOTAL>>>();
    finalize_kernel<<<1, 256>>>(out);
}